// round 14
// baseline (speedup 1.0000x reference)
#include <cuda_runtime.h>
#include <cstdint>

// Problem constants
#define BB 8
#define SS 4096
#define AA 3
#define KK 64
#define MARGIN 5.0f
#define ROWS (BB * SS)          // 32768
#define FLATN (SS * AA)         // 12288 per batch

// Output layout (float32):
//   [0] loss | [1..) predict_label (B,S,A) | total_idx (B*K,3) | candidate_label (B*K)
#define OFF_PRED 1
#define OFF_TI   (1 + ROWS * AA)            // 98305
#define OFF_CAND (OFF_TI + BB * KK * 3)     // 99841

#define NBLK 888    // 148 SMs x 6 blocks -> exactly one wave
#define MAXR 37     // blocks 0..799 take 37 rows, 800..887 take 36
#define DEPTH 4     // cp.async ring depth
#define STAGE_BYTES (DEPTH * 4096)       // 16 KB dynamic smem per block
#define TROWS 8     // epilogue tile
#define PR 583      // floats per tile-row in partial buffer (pad vs bank conflicts)

// Scratch (static device globals -- no allocations allowed)
__device__ float g_logits[ROWS * 6];     // full logits (768 KB)
__device__ int   g_selflat[BB * KK];     // selected flat indices
__device__ int   g_ctr;                  // completion counter (reset each run)

__device__ __forceinline__ void cp16(uint32_t dst_smem, const void* src) {
    asm volatile("cp.async.cg.shared.global [%0], [%1], 16;"
                 :: "r"(dst_smem), "l"(src));
}
#define CP_COMMIT()  asm volatile("cp.async.commit_group;" ::: "memory")
#define CP_WAIT3()   asm volatile("cp.async.wait_group 3;" ::: "memory")

// ---------------------------------------------------------------------------
// Single fused kernel, 128 threads (4 warps), occ 6 (24 warps/SM).
//  Phase A (blocks 880..887): per-batch selection. Positives forced to exactly
//    2.0 (> any sigmoid < 1), stable top_k => first 64 ascending flat positions
//    with label==1. Labels are INT32 (jax x64 off).
//  Phase B (all blocks): X @ W + bias -> logits + predict_label.
//    4 warps per row; thread t owns d in {4t..4t+3} U {512+4t..512+4t+3}
//    (48 W regs). cp.async ring (R13-verified self-sync: each thread copies
//    exactly the 2x16B chunks it later reads). Reduction: ONE shfl fold at
//    offset 16 (6 SHFL) -> 32 lanes store 3 partials each to a pad-strided
//    smem buffer -> tiled epilogue (every 8 rows) finishes the 64-way sums.
//  Phase C (last block): candidate_label + margin loss (fixed order).
// ---------------------------------------------------------------------------
__global__ void __launch_bounds__(128, 6)
k_fused(const float* __restrict__ X, const float* __restrict__ W,
        const float* __restrict__ bias, const int* __restrict__ labels,
        float* __restrict__ out)
{
    extern __shared__ float4 stage[];           // [DEPTH][256] float4 (16 KB)
    __shared__ float sP[TROWS * PR];            // lane partials (18.7 KB)
    __shared__ float sFin[MAXR * 6];            // [row][k] final logits
    __shared__ int   s_idx[KK];
    __shared__ int   s_cnt[4];
    __shared__ float s_red[4];
    __shared__ int   s_flag;

    const int t    = threadIdx.x;        // 0..127
    const int warp = t >> 5;
    const int lane = t & 31;
    const int bid  = blockIdx.x;

    // ---------------- Phase A: selection (blocks 880..887) ----------------
    if (bid >= NBLK - BB) {
        const int b = bid - (NBLK - BB);
        const int* lab = labels + (size_t)b * FLATN;

        int found = 0;  // uniform across threads
        for (int base = 0; base < FLATN && found < KK; base += 128) {
            const int v = (lab[base + t] == 1);
            const unsigned m = __ballot_sync(0xffffffffu, v);
            if (lane == 0) s_cnt[warp] = __popc(m);
            __syncthreads();

            int wbase = found;
            for (int w = 0; w < warp; w++) wbase += s_cnt[w];
            const int g = wbase + __popc(m & ((1u << lane) - 1u));
            if (v && g < KK) s_idx[g] = base + t;

            int tot = 0;
#pragma unroll
            for (int w = 0; w < 4; w++) tot += s_cnt[w];
            found += tot;
            __syncthreads();
        }
        if (t < KK) {
            const int flat = s_idx[t];
            const int s = flat / AA;
            const int a = flat - s * AA;
            const size_t samp = (size_t)b * KK + t;
            g_selflat[samp] = flat;
            out[OFF_TI + samp * 3 + 0] = (float)b;
            out[OFF_TI + samp * 3 + 1] = (float)s;
            out[OFF_TI + samp * 3 + 2] = (float)a;
        }
        __syncthreads();   // smem reused below
    }

    // ---------------- Phase B: GEMM + logits + predict_label ----------------
    const int start = bid * 36 + min(bid, 800);
    const int nr    = 36 + (bid < 800 ? 1 : 0);

    // wA[j*6+k] = W[4t + j][k],  wB[j*6+k] = W[512 + 4t + j][k]
    float wA[24], wB[24];
#pragma unroll
    for (int i = 0; i < 24; i++) {
        wA[i] = W[t * 24 + i];
        wB[i] = W[(512 + 4 * t) * 6 + i];
    }

    const float4* __restrict__ X4 = reinterpret_cast<const float4*>(X);

    uint32_t stageB;
    asm("{ .reg .u64 tt; cvta.to.shared.u64 tt, %1; cvt.u32.u64 %0, tt; }"
        : "=r"(stageB) : "l"(stage));
    const uint32_t myA  = stageB + (uint32_t)t * 16;          // slot 0, xa chunk
    const uint32_t myBq = myA + 2048;                          // xb chunk

    // Preload DEPTH rows (one commit-group per row; nr >= 36 > DEPTH).
#pragma unroll
    for (int i = 0; i < DEPTH; i++) {
        const float4* srow = X4 + (size_t)(start + i) * 256 + t;
        cp16(myA  + (uint32_t)i * 4096, srow);
        cp16(myBq + (uint32_t)i * 4096, srow + 128);
        CP_COMMIT();
    }

    const int hl = lane & 15;            // half-lane within fold
    const int ks = lane >> 4;            // kset: 0 -> k012, 1 -> k345

    for (int tbase = 0; tbase < nr; tbase += TROWS) {
        const int tn = min(TROWS, nr - tbase);

        for (int i = 0; i < tn; i++) {
            const int r = tbase + i;
            CP_WAIT3();                              // row r resident
            const int slot = r & (DEPTH - 1);
            const float4* sl = stage + slot * 256;
            const float4 ca = sl[t];
            const float4 cb = sl[128 + t];

            // Refill this slot with row r+DEPTH; uniform commit count per iter.
            const int rf = r + DEPTH;
            if (rf < nr) {
                const float4* srow = X4 + (size_t)(start + rf) * 256 + t;
                cp16(myA  + (uint32_t)slot * 4096, srow);
                cp16(myBq + (uint32_t)slot * 4096, srow + 128);
            }
            CP_COMMIT();

            const float xav[4] = {ca.x, ca.y, ca.z, ca.w};
            const float xbv[4] = {cb.x, cb.y, cb.z, cb.w};
            float acc[6];
#pragma unroll
            for (int k = 0; k < 6; k++) acc[k] = 0.0f;
#pragma unroll
            for (int j = 0; j < 4; j++)
#pragma unroll
                for (int k = 0; k < 6; k++) {
                    acc[k] = fmaf(xav[j], wA[j * 6 + k], acc[k]);
                    acc[k] = fmaf(xbv[j], wB[j * 6 + k], acc[k]);
                }

            // ONE fold at offset 16: acc[k] += lane^16's acc[k].
#pragma unroll
            for (int k = 0; k < 6; k++)
                acc[k] += __shfl_xor_sync(0xffffffffu, acc[k], 16);

            // All 32 lanes store 3 partials: kset0 -> k012 @ +0..2,
            // kset1 -> k345 @ +4..6. Lane-slot stride 9, row stride PR.
            float* dst = &sP[i * PR + (warp * 16 + hl) * 9 + ks * 4];
            dst[0] = acc[ks * 3 + 0];
            dst[1] = acc[ks * 3 + 1];
            dst[2] = acc[ks * 3 + 2];
        }
        __syncthreads();

        // Epilogue: 48 threads, each finishes one (row, k): 64 partials.
        if (t < TROWS * 6) {
            const int row = t / 6;
            const int k   = t - row * 6;
            if (row < tn) {
                const int koff = (k < 3) ? k : (k + 1);
                const float* p = &sP[row * PR + koff];
                float s0 = 0.0f, s1 = 0.0f, s2 = 0.0f, s3 = 0.0f;
#pragma unroll
                for (int i = 0; i < 64; i += 4) {
                    s0 += p[(i + 0) * 9];
                    s1 += p[(i + 1) * 9];
                    s2 += p[(i + 2) * 9];
                    s3 += p[(i + 3) * 9];
                }
                const float s = __ldg(&bias[k]) + ((s0 + s1) + (s2 + s3));
                g_logits[(size_t)(start + tbase + row) * 6 + k] = s;
                sFin[(tbase + row) * 6 + k] = s;
            }
        }
        __syncthreads();
    }

    // predict_label: argmax over C=2, first-max tie-break => 1 iff p1 > p0.
    for (int u = t; u < nr * 3; u += 128) {
        const int row = u / 3;
        const int a   = u - row * 3;
        out[OFF_PRED + (size_t)(start + row) * 3 + a] =
            (sFin[row * 6 + 2 * a + 1] > sFin[row * 6 + 2 * a]) ? 1.0f : 0.0f;
    }

    // ---------------- Phase C: last block computes loss + candidate ----------
    __threadfence();
    if (t == 0) s_flag = (atomicAdd(&g_ctr, 1) == NBLK - 1) ? 1 : 0;
    __syncthreads();
    if (!s_flag) return;
    __threadfence();   // acquire: all blocks' logits/selflat visible

    float term = 0.0f;
#pragma unroll
    for (int i = 0; i < 4; i++) {
        const int samp = t + i * 128;                 // 512 samples total
        const int flat = g_selflat[samp];
        const int b2 = samp >> 6;                     // samp / KK
        const int s2 = flat / AA;
        const int a2 = flat - s2 * AA;
        const int row = b2 * SS + s2;
        const float p0 = g_logits[(size_t)row * 6 + 2 * a2];
        const float p1 = g_logits[(size_t)row * 6 + 2 * a2 + 1];
        out[OFF_CAND + samp] = (p1 > p0) ? 1.0f : 0.0f;
        // selected positions always have label 1 => y = 1; C = 2
        term += fmaxf(0.0f, MARGIN - p1 + p0) * 0.5f;
    }
#pragma unroll
    for (int off = 16; off > 0; off >>= 1)
        term += __shfl_xor_sync(0xffffffffu, term, off);
    if (lane == 0) s_red[warp] = term;
    __syncthreads();
    if (t == 0) {
        float tot = 0.0f;
#pragma unroll
        for (int w = 0; w < 4; w++) tot += s_red[w];
        out[0] = tot / (float)(BB * KK);
        g_ctr = 0;   // ready for next graph replay
    }
}

// ---------------------------------------------------------------------------
extern "C" void kernel_launch(void* const* d_in, const int* in_sizes, int n_in,
                              void* d_out, int out_size)
{
    const float* X      = (const float*)d_in[0];    // (B,S,D) f32
    const float* W      = (const float*)d_in[1];    // (D, A*C) f32
    const float* bias   = (const float*)d_in[2];    // (A*C,) f32
    const int*   labels = (const int*)d_in[3];      // (B,S,A) int32 (jax x64 off)
    float*       out    = (float*)d_out;

    // Not an allocation; deterministic; capture-safe.
    cudaFuncSetAttribute(k_fused, cudaFuncAttributeMaxDynamicSharedMemorySize,
                         STAGE_BYTES);
    k_fused<<<NBLK, 128, STAGE_BYTES>>>(X, W, bias, labels, out);
}

// round 15
// speedup vs baseline: 1.3418x; 1.3418x over previous
#include <cuda_runtime.h>
#include <cstdint>

// Problem constants
#define BB 8
#define SS 4096
#define AA 3
#define KK 64
#define MARGIN 5.0f
#define ROWS (BB * SS)          // 32768
#define FLATN (SS * AA)         // 12288 per batch

// Output layout (float32):
//   [0] loss | [1..) predict_label (B,S,A) | total_idx (B*K,3) | candidate_label (B*K)
#define OFF_PRED 1
#define OFF_TI   (1 + ROWS * AA)            // 98305
#define OFF_CAND (OFF_TI + BB * KK * 3)     // 99841

#define NBLK 444    // 148 SMs x 3+ blocks; target occupancy 4 -> 1.0 wave at 444<592
#define MAXR 37     // teams 0..799 take 37 rows, 800..887 take 36
#define DEPTH 6     // cp.async ring depth (rows per team in flight)
#define STAGE_BYTES (2 * DEPTH * 4096)   // 48 KB dynamic smem per block

// Scratch (static device globals -- no allocations allowed)
__device__ float g_logits[ROWS * 6];     // full logits (768 KB)
__device__ int   g_selflat[BB * KK];     // selected flat indices
__device__ int   g_ctr;                  // completion counter (reset each run)

__device__ __forceinline__ void cp16(uint32_t dst_smem, const void* src) {
    asm volatile("cp.async.cg.shared.global [%0], [%1], 16;"
                 :: "r"(dst_smem), "l"(src));
}
#define CP_COMMIT()  asm volatile("cp.async.commit_group;" ::: "memory")
#define CP_WAIT5()   asm volatile("cp.async.wait_group 5;" ::: "memory")

// ---------------------------------------------------------------------------
// Single fused kernel, 128 threads (4 warps), target occupancy 4 (16 warps/SM).
// Identical algorithm to the verified 36.9us R9 kernel; deltas: DEPTH 8->6,
// launch_bounds occ 3->4, float4 lanes used directly in FMA (register trim).
//  Phase A (blocks 436..443): per-batch selection. Positives forced to exactly
//    2.0 (> any sigmoid < 1), stable top_k => first 64 ascending flat positions
//    with label==1. Labels are INT32 (jax x64 off).
//  Phase B (all blocks): X @ W + bias -> logits + predict_label.
//    2 warps per row-team; lane owns d = jq*256 + wu*128 + lane*4 + jj (96 W
//    regs). X rows stream through a 6-deep cp.async smem ring; each thread
//    copies exactly the 4x16B chunks it later reads -> its own wait_group is
//    the only sync needed. 18-SHFL folded butterfly per warp; 2 warp partials
//    combined in smem. Deterministic.
//  Phase C (last block): candidate_label + margin loss (fixed order).
// ---------------------------------------------------------------------------
__global__ void __launch_bounds__(128, 4)
k_fused(const float* __restrict__ X, const float* __restrict__ W,
        const float* __restrict__ bias, const int* __restrict__ labels,
        float* __restrict__ out)
{
    extern __shared__ float4 stage[];           // [2][DEPTH][256] float4
    __shared__ float sPart[2 * MAXR * 2 * 6];   // [team][row][warp-in-team][k]
    __shared__ float sFin[2 * MAXR * 6];        // [team][row][k]
    __shared__ int   s_idx[KK];
    __shared__ int   s_cnt[4];
    __shared__ float s_red[4];
    __shared__ int   s_flag;

    const int t    = threadIdx.x;        // 0..127
    const int warp = t >> 5;
    const int lane = t & 31;
    const int bid  = blockIdx.x;

    // ---------------- Phase A: selection (blocks 436..443) ----------------
    if (bid >= NBLK - BB) {
        const int b = bid - (NBLK - BB);
        const int* lab = labels + (size_t)b * FLATN;

        int found = 0;  // uniform across threads
        for (int base = 0; base < FLATN && found < KK; base += 128) {
            const int v = (lab[base + t] == 1);
            const unsigned m = __ballot_sync(0xffffffffu, v);
            if (lane == 0) s_cnt[warp] = __popc(m);
            __syncthreads();

            int wbase = found;
            for (int w = 0; w < warp; w++) wbase += s_cnt[w];
            const int g = wbase + __popc(m & ((1u << lane) - 1u));
            if (v && g < KK) s_idx[g] = base + t;

            int tot = 0;
#pragma unroll
            for (int w = 0; w < 4; w++) tot += s_cnt[w];
            found += tot;
            __syncthreads();
        }
        if (t < KK) {
            const int flat = s_idx[t];
            const int s = flat / AA;
            const int a = flat - s * AA;
            const size_t samp = (size_t)b * KK + t;
            g_selflat[samp] = flat;
            out[OFF_TI + samp * 3 + 0] = (float)b;
            out[OFF_TI + samp * 3 + 1] = (float)s;
            out[OFF_TI + samp * 3 + 2] = (float)a;
        }
        __syncthreads();   // smem reused below
    }

    // ---------------- Phase B: GEMM + logits + predict_label ----------------
    const int tw   = warp >> 1;              // team within block (0,1)
    const int wu   = warp & 1;               // warp within team
    const int team = bid * 2 + tw;           // 0..887
    const int start = team * 36 + min(team, 800);
    const int nr    = 36 + (team < 800 ? 1 : 0);

    // 96 W coefficients; lane owns d = jq*256 + wu*128 + lane*4 + jj
    float wR[96];
#pragma unroll
    for (int jq = 0; jq < 4; jq++)
#pragma unroll
        for (int jj = 0; jj < 4; jj++)
#pragma unroll
            for (int k = 0; k < 6; k++)
                wR[jq * 24 + jj * 6 + k] =
                    W[(jq * 256 + wu * 128 + lane * 4 + jj) * 6 + k];

    const float4* __restrict__ X4 = reinterpret_cast<const float4*>(X);
    const int cf4 = wu * 32 + lane;          // f4 offset within row-quarter

    uint32_t stageB;
    asm("{ .reg .u64 tt; cvta.to.shared.u64 tt, %1; cvt.u32.u64 %0, tt; }"
        : "=r"(stageB) : "l"(stage));
    const uint32_t my0 = stageB + (uint32_t)tw * (DEPTH * 4096)
                       + (uint32_t)cf4 * 16;

    // Preload DEPTH rows (one commit-group per row; nr >= 36 > DEPTH).
#pragma unroll
    for (int i = 0; i < DEPTH; i++) {
        const float4* srow = X4 + (size_t)(start + i) * 256 + cf4;
        const uint32_t db = my0 + (uint32_t)i * 4096;
        cp16(db +    0, srow +   0);
        cp16(db + 1024, srow +  64);
        cp16(db + 2048, srow + 128);
        cp16(db + 3072, srow + 192);
        CP_COMMIT();
    }

    int slot = 0;
    for (int r = 0; r < nr; r++) {
        CP_WAIT5();                              // oldest group (row r) resident
        const float4* sl = stage + (tw * DEPTH + slot) * 256 + cf4;
        const float4 c0 = sl[0];
        const float4 c1 = sl[64];
        const float4 c2 = sl[128];
        const float4 c3 = sl[192];

        // Refill this slot with row r+DEPTH; uniform commit count per iter.
        const int rf = r + DEPTH;
        if (rf < nr) {
            const float4* srow = X4 + (size_t)(start + rf) * 256 + cf4;
            const uint32_t db = my0 + (uint32_t)slot * 4096;
            cp16(db +    0, srow +   0);
            cp16(db + 1024, srow +  64);
            cp16(db + 2048, srow + 128);
            cp16(db + 3072, srow + 192);
        }
        CP_COMMIT();
        if (++slot == DEPTH) slot = 0;

        float acc[6];
#pragma unroll
        for (int k = 0; k < 6; k++) acc[k] = 0.0f;
#pragma unroll
        for (int k = 0; k < 6; k++) {
            acc[k] = fmaf(c0.x, wR[ 0 + k], acc[k]);
            acc[k] = fmaf(c0.y, wR[ 6 + k], acc[k]);
            acc[k] = fmaf(c0.z, wR[12 + k], acc[k]);
            acc[k] = fmaf(c0.w, wR[18 + k], acc[k]);
            acc[k] = fmaf(c1.x, wR[24 + k], acc[k]);
            acc[k] = fmaf(c1.y, wR[30 + k], acc[k]);
            acc[k] = fmaf(c1.z, wR[36 + k], acc[k]);
            acc[k] = fmaf(c1.w, wR[42 + k], acc[k]);
            acc[k] = fmaf(c2.x, wR[48 + k], acc[k]);
            acc[k] = fmaf(c2.y, wR[54 + k], acc[k]);
            acc[k] = fmaf(c2.z, wR[60 + k], acc[k]);
            acc[k] = fmaf(c2.w, wR[66 + k], acc[k]);
            acc[k] = fmaf(c3.x, wR[72 + k], acc[k]);
            acc[k] = fmaf(c3.y, wR[78 + k], acc[k]);
            acc[k] = fmaf(c3.z, wR[84 + k], acc[k]);
            acc[k] = fmaf(c3.w, wR[90 + k], acc[k]);
        }

        // 18-SHFL folded butterfly: stage 16 folds 6 accs -> 3 per half-warp.
        float o[6];
#pragma unroll
        for (int k = 0; k < 6; k++) o[k] = __shfl_xor_sync(0xffffffffu, acc[k], 16);
        float q0, q1, q2;
        if (lane < 16) { q0 = acc[0] + o[0]; q1 = acc[1] + o[1]; q2 = acc[2] + o[2]; }
        else           { q0 = acc[3] + o[3]; q1 = acc[4] + o[4]; q2 = acc[5] + o[5]; }
#pragma unroll
        for (int off = 8; off > 0; off >>= 1) {
            q0 += __shfl_xor_sync(0xffffffffu, q0, off);
            q1 += __shfl_xor_sync(0xffffffffu, q1, off);
            q2 += __shfl_xor_sync(0xffffffffu, q2, off);
        }
        float* dst = &sPart[((tw * MAXR + r) * 2 + wu) * 6];
        if (lane == 0)  { dst[0] = q0; dst[1] = q1; dst[2] = q2; }
        if (lane == 16) { dst[3] = q0; dst[4] = q1; dst[5] = q2; }
    }
    __syncthreads();

    // Cross-warp (2 partials) combine + bias; write logits, keep in smem.
    for (int v = t; v < 2 * nr * 6; v += 128) {
        const int tw2 = v / (nr * 6);
        const int rem = v - tw2 * nr * 6;
        const int row = rem / 6;
        const int k   = rem - row * 6;
        const int team2 = bid * 2 + tw2;
        const int st2   = team2 * 36 + min(team2, 800);
        float s = __ldg(&bias[k])
                + sPart[((tw2 * MAXR + row) * 2 + 0) * 6 + k]
                + sPart[((tw2 * MAXR + row) * 2 + 1) * 6 + k];
        g_logits[(size_t)(st2 + row) * 6 + k] = s;
        sFin[(tw2 * MAXR + row) * 6 + k] = s;
    }
    __syncthreads();

    // predict_label: argmax over C=2, first-max tie-break => 1 iff p1 > p0.
    for (int u = t; u < 2 * nr * 3; u += 128) {
        const int tw2 = u / (nr * 3);
        const int rem = u - tw2 * nr * 3;
        const int row = rem / 3;
        const int a   = rem - row * 3;
        const int team2 = bid * 2 + tw2;
        const int st2   = team2 * 36 + min(team2, 800);
        out[OFF_PRED + (size_t)(st2 + row) * 3 + a] =
            (sFin[(tw2 * MAXR + row) * 6 + 2 * a + 1] >
             sFin[(tw2 * MAXR + row) * 6 + 2 * a]) ? 1.0f : 0.0f;
    }

    // ---------------- Phase C: last block computes loss + candidate ----------
    __threadfence();
    if (t == 0) s_flag = (atomicAdd(&g_ctr, 1) == NBLK - 1) ? 1 : 0;
    __syncthreads();
    if (!s_flag) return;
    __threadfence();   // acquire: all blocks' logits/selflat visible

    float term = 0.0f;
#pragma unroll
    for (int i = 0; i < 4; i++) {
        const int samp = t + i * 128;                 // 512 samples total
        const int flat = g_selflat[samp];
        const int b2 = samp >> 6;                     // samp / KK
        const int s2 = flat / AA;
        const int a2 = flat - s2 * AA;
        const int row = b2 * SS + s2;
        const float p0 = g_logits[(size_t)row * 6 + 2 * a2];
        const float p1 = g_logits[(size_t)row * 6 + 2 * a2 + 1];
        out[OFF_CAND + samp] = (p1 > p0) ? 1.0f : 0.0f;
        // selected positions always have label 1 => y = 1; C = 2
        term += fmaxf(0.0f, MARGIN - p1 + p0) * 0.5f;
    }
#pragma unroll
    for (int off = 16; off > 0; off >>= 1)
        term += __shfl_xor_sync(0xffffffffu, term, off);
    if (lane == 0) s_red[warp] = term;
    __syncthreads();
    if (t == 0) {
        float tot = 0.0f;
#pragma unroll
        for (int w = 0; w < 4; w++) tot += s_red[w];
        out[0] = tot / (float)(BB * KK);
        g_ctr = 0;   // ready for next graph replay
    }
}

// ---------------------------------------------------------------------------
extern "C" void kernel_launch(void* const* d_in, const int* in_sizes, int n_in,
                              void* d_out, int out_size)
{
    const float* X      = (const float*)d_in[0];    // (B,S,D) f32
    const float* W      = (const float*)d_in[1];    // (D, A*C) f32
    const float* bias   = (const float*)d_in[2];    // (A*C,) f32
    const int*   labels = (const int*)d_in[3];      // (B,S,A) int32 (jax x64 off)
    float*       out    = (float*)d_out;

    // Not an allocation; deterministic; capture-safe.
    cudaFuncSetAttribute(k_fused, cudaFuncAttributeMaxDynamicSharedMemorySize,
                         STAGE_BYTES);
    k_fused<<<NBLK, 128, STAGE_BYTES>>>(X, W, bias, labels, out);
}